// round 6
// baseline (speedup 1.0000x reference)
#include <cuda_runtime.h>

// Problem constants (match reference)
#define BB 32
#define TT 512
#define DD 512
#define EE 8
#define HH 2048

#define FINAL_ELEMS (BB * TT * DD)   // 8388608

// ---------------- scratch (device globals; no allocation allowed) ----------
__device__ __align__(16) float g_h[(size_t)BB * TT * HH];   // [B, T, H] hidden
__device__ int g_expert[BB];

// ---------------- packed f32x2 helpers -------------------------------------
__device__ __forceinline__ unsigned long long pack2(float lo, float hi) {
    unsigned long long r;
    asm("mov.b64 %0, {%1, %2};"
        : "=l"(r) : "r"(__float_as_uint(lo)), "r"(__float_as_uint(hi)));
    return r;
}
__device__ __forceinline__ void unpack2(unsigned long long v, float& lo, float& hi) {
    unsigned int a, b;
    asm("mov.b64 {%0, %1}, %2;" : "=r"(a), "=r"(b) : "l"(v));
    lo = __uint_as_float(a);
    hi = __uint_as_float(b);
}
__device__ __forceinline__ void fma2(unsigned long long& d,
                                     unsigned long long a, unsigned long long b) {
    // packed dual-FMA: {d.lo,d.hi} = {a.lo*b.lo+d.lo, a.hi*b.hi+d.hi}
    asm("fma.rn.f32x2 %0, %1, %2, %0;" : "+l"(d) : "l"(a), "l"(b));
}

// ---------------- router: mean-pool -> 512x8 GEMV -> softmax -> argmax -----
__global__ void router_kernel(const float* __restrict__ x,
                              const float* __restrict__ Wp,
                              const float* __restrict__ bp,
                              float* __restrict__ out,
                              int write_aux) {
    __shared__ float pooled[DD];
    __shared__ float logits[EE];
    const int b = blockIdx.x;
    const float* xb = x + (size_t)b * TT * DD;

    // mean over T: thread d accumulates column d (coalesced across warp)
    for (int d = threadIdx.x; d < DD; d += blockDim.x) {
        float s0 = 0.f, s1 = 0.f, s2 = 0.f, s3 = 0.f;
        #pragma unroll 4
        for (int t = 0; t < TT; t += 4) {
            s0 += xb[(size_t)(t + 0) * DD + d];
            s1 += xb[(size_t)(t + 1) * DD + d];
            s2 += xb[(size_t)(t + 2) * DD + d];
            s3 += xb[(size_t)(t + 3) * DD + d];
        }
        pooled[d] = ((s0 + s1) + (s2 + s3)) * (1.0f / TT);
    }
    __syncthreads();

    const int warp = threadIdx.x >> 5;
    const int lane = threadIdx.x & 31;
    if (warp < EE) {
        float s = 0.f;
        for (int d = lane; d < DD; d += 32) s += pooled[d] * Wp[d * EE + warp];
        #pragma unroll
        for (int o = 16; o > 0; o >>= 1) s += __shfl_xor_sync(0xFFFFFFFFu, s, o);
        if (lane == 0) logits[warp] = s + bp[warp];
    }
    __syncthreads();

    if (threadIdx.x == 0) {
        float mx = logits[0];
        int arg = 0;
        #pragma unroll
        for (int e = 1; e < EE; e++)
            if (logits[e] > mx) { mx = logits[e]; arg = e; }
        float ex[EE], den = 0.f;
        #pragma unroll
        for (int e = 0; e < EE; e++) { ex[e] = expf(logits[e] - mx); den += ex[e]; }
        if (write_aux) {
            const float inv = 1.0f / den;
            #pragma unroll
            for (int e = 0; e < EE; e++)
                out[FINAL_ELEMS + b * EE + e] = ex[e] * inv;
            out[FINAL_ELEMS + BB * EE + b] = (float)arg;
        }
        g_expert[b] = arg;
    }
}

// ---------------- tiled SGEMM body (128x128x16, 8x8 microtile, f32x2) ------
#define BM 128
#define BN 128
#define BK 16
#define BMP (BM + 4)   // pad A-smem rows to soften transpose-store conflicts

template<bool RELU>
__device__ __forceinline__ void gemm_body(const float* __restrict__ A,   // [M,K]
                                          const float* __restrict__ Bm,  // [K,N]
                                          const float* __restrict__ bias,// [N]
                                          float* __restrict__ C,         // [M,N]
                                          int N, int K) {
    __shared__ float As[BK][BMP];
    __shared__ float Bs[BK][BN];

    const int tid = threadIdx.x;
    const int tx = tid & 15;         // 0..15 -> 8 N-cols each
    const int ty = tid >> 4;         // 0..15 -> 8 M-rows each
    const int row0 = blockIdx.y * BM;
    const int col0 = blockIdx.x * BN;

    // A loads: 128 rows x 16 cols = 512 float4, 2 per thread
    const int arow  = tid >> 2;          // 0..63
    const int acol  = (tid & 3) * 4;     // 0,4,8,12
    // B loads: 16 rows x 128 cols = 512 float4, 2 per thread
    const int brow  = tid >> 5;          // 0..7
    const int bcol  = (tid & 31) * 4;

    unsigned long long acc[8][4];        // 8 rows x 4 packed col-pairs
    #pragma unroll
    for (int i = 0; i < 8; i++)
        #pragma unroll
        for (int j = 0; j < 4; j++) acc[i][j] = 0ULL;   // bits of {0.f,0.f}

    for (int kt = 0; kt < K; kt += BK) {
        // stage A (transposed into smem)
        #pragma unroll
        for (int r = 0; r < 2; r++) {
            const int row = arow + r * 64;
            const float4 v = *(const float4*)&A[(size_t)(row0 + row) * K + kt + acol];
            As[acol + 0][row] = v.x;
            As[acol + 1][row] = v.y;
            As[acol + 2][row] = v.z;
            As[acol + 3][row] = v.w;
        }
        // stage B
        #pragma unroll
        for (int r = 0; r < 2; r++) {
            const int row = brow + r * 8;
            *(float4*)&Bs[row][bcol] =
                *(const float4*)&Bm[(size_t)(kt + row) * N + col0 + bcol];
        }
        __syncthreads();

        #pragma unroll
        for (int k = 0; k < BK; k++) {
            const float4 a0 = *(const float4*)&As[k][ty * 8];
            const float4 a1 = *(const float4*)&As[k][ty * 8 + 4];
            const float4 b0 = *(const float4*)&Bs[k][tx * 8];
            const float4 b1 = *(const float4*)&Bs[k][tx * 8 + 4];
            unsigned long long bp2[4];
            bp2[0] = pack2(b0.x, b0.y);
            bp2[1] = pack2(b0.z, b0.w);
            bp2[2] = pack2(b1.x, b1.y);
            bp2[3] = pack2(b1.z, b1.w);
            const float av[8] = {a0.x, a0.y, a0.z, a0.w, a1.x, a1.y, a1.z, a1.w};
            #pragma unroll
            for (int i = 0; i < 8; i++) {
                const unsigned long long a2 = pack2(av[i], av[i]);
                #pragma unroll
                for (int j = 0; j < 4; j++) fma2(acc[i][j], a2, bp2[j]);
            }
        }
        __syncthreads();
    }

    // epilogue: +bias, optional relu, float2 stores
    #pragma unroll
    for (int i = 0; i < 8; i++) {
        const int row = row0 + ty * 8 + i;
        #pragma unroll
        for (int j = 0; j < 4; j++) {
            const int col = col0 + tx * 8 + j * 2;
            float lo, hi;
            unpack2(acc[i][j], lo, hi);
            lo += bias[col];
            hi += bias[col + 1];
            if (RELU) { lo = fmaxf(lo, 0.f); hi = fmaxf(hi, 0.f); }
            float2 v; v.x = lo; v.y = hi;
            *(float2*)&C[(size_t)row * N + col] = v;
        }
    }
}

// GEMM1: h = relu(x @ W1[e] + b1[e])    M=T=512, N=H=2048, K=D=512
__global__ void __launch_bounds__(256)
gemm1_kernel(const float* __restrict__ x,
             const float* __restrict__ W1,
             const float* __restrict__ b1) {
    const int b = blockIdx.z;
    const int e = g_expert[b];
    gemm_body<true>(x + (size_t)b * TT * DD,
                    W1 + (size_t)e * DD * HH,
                    b1 + (size_t)e * HH,
                    g_h + (size_t)b * TT * HH,
                    HH, DD);
}

// GEMM2: out = h @ W2[e] + b2[e]        M=T=512, N=D=512, K=H=2048
__global__ void __launch_bounds__(256)
gemm2_kernel(const float* __restrict__ W2,
             const float* __restrict__ b2,
             float* __restrict__ out) {
    const int b = blockIdx.z;
    const int e = g_expert[b];
    gemm_body<false>(g_h + (size_t)b * TT * HH,
                     W2 + (size_t)e * HH * DD,
                     b2 + (size_t)e * DD,
                     out + (size_t)b * TT * DD,
                     DD, HH);
}

// ---------------- launch ----------------------------------------------------
extern "C" void kernel_launch(void* const* d_in, const int* in_sizes, int n_in,
                              void* d_out, int out_size) {
    const float* x  = (const float*)d_in[0];
    const float* Wp = (const float*)d_in[1];
    const float* bp = (const float*)d_in[2];
    const float* W1 = (const float*)d_in[3];
    const float* b1 = (const float*)d_in[4];
    const float* W2 = (const float*)d_in[5];
    const float* b2 = (const float*)d_in[6];
    float* out = (float*)d_out;

    // only write probs/chosen if the output buffer actually carries them
    const int write_aux = (out_size >= FINAL_ELEMS + BB * EE + BB) ? 1 : 0;

    router_kernel<<<BB, 256>>>(x, Wp, bp, out, write_aux);
    gemm1_kernel<<<dim3(HH / BN, TT / BM, BB), 256>>>(x, W1, b1);
    gemm2_kernel<<<dim3(DD / BN, TT / BM, BB), 256>>>(W2, b2, out);
}

// round 9
// speedup vs baseline: 2.3781x; 2.3781x over previous
#include <cuda_runtime.h>
#include <cuda_bf16.h>
#include <cstdint>

// Problem constants
#define BB 32
#define TT 512
#define DD 512
#define EE 8
#define HH 2048
#define FINAL_ELEMS (BB * TT * DD)

// ---------------- device scratch (no allocation allowed) --------------------
__device__ int g_expert[BB];
__device__ float g_pool_part[BB][16][DD];
__device__ __align__(16) __nv_bfloat16 g_x_hi[(size_t)BB * TT * DD];
__device__ __align__(16) __nv_bfloat16 g_x_lo[(size_t)BB * TT * DD];
__device__ __align__(16) __nv_bfloat16 g_w1_hi[(size_t)EE * HH * DD]; // [E][H][D] (K-major)
__device__ __align__(16) __nv_bfloat16 g_w1_lo[(size_t)EE * HH * DD];
__device__ __align__(16) __nv_bfloat16 g_w2_hi[(size_t)EE * DD * HH]; // [E][D][H] (K-major)
__device__ __align__(16) __nv_bfloat16 g_w2_lo[(size_t)EE * DD * HH];
__device__ __align__(16) __nv_bfloat16 g_h_hi[(size_t)BB * TT * HH];
__device__ __align__(16) __nv_bfloat16 g_h_lo[(size_t)BB * TT * HH];

// ---------------- PTX helpers (base-target only: cp.async/ldmatrix/mma) -----
__device__ __forceinline__ uint32_t smem_u32(const void* p) {
    uint32_t a;
    asm("{ .reg .u64 t; cvta.to.shared.u64 t, %1; cvt.u32.u64 %0, t; }" : "=r"(a) : "l"(p));
    return a;
}
#define CP_ASYNC16(s, g) \
    asm volatile("cp.async.cg.shared.global [%0], [%1], 16;" :: "r"(s), "l"(g))
#define CP_COMMIT() asm volatile("cp.async.commit_group;")
#define CP_WAIT(n)  asm volatile("cp.async.wait_group %0;" :: "n"(n))

__device__ __forceinline__ void ldsm4(uint32_t* r, uint32_t a) {
    asm volatile("ldmatrix.sync.aligned.m8n8.x4.shared.b16 {%0,%1,%2,%3}, [%4];"
                 : "=r"(r[0]), "=r"(r[1]), "=r"(r[2]), "=r"(r[3]) : "r"(a));
}
__device__ __forceinline__ void mma16816(float* c, const uint32_t* a, const uint32_t* b) {
    asm volatile("mma.sync.aligned.m16n8k16.row.col.f32.bf16.bf16.f32 "
                 "{%0,%1,%2,%3}, {%4,%5,%6,%7}, {%8,%9}, {%0,%1,%2,%3};"
                 : "+f"(c[0]), "+f"(c[1]), "+f"(c[2]), "+f"(c[3])
                 : "r"(a[0]), "r"(a[1]), "r"(a[2]), "r"(a[3]), "r"(b[0]), "r"(b[1]));
}

__device__ __forceinline__ void split2(float v, __nv_bfloat16& h, __nv_bfloat16& l) {
    h = __float2bfloat16(v);
    l = __float2bfloat16(v - __bfloat162float(h));
}

// ---------------- conversion kernels ---------------------------------------
__global__ void split_x_kernel(const float* __restrict__ x) {
    size_t i = ((size_t)blockIdx.x * 256 + threadIdx.x) * 4;
    float4 v = *(const float4*)(x + i);
    __nv_bfloat16 h0, l0, h1, l1, h2, l2, h3, l3;
    split2(v.x, h0, l0); split2(v.y, h1, l1); split2(v.z, h2, l2); split2(v.w, h3, l3);
    uint2 ph, pl;
    ph.x = ((uint32_t)__bfloat16_as_ushort(h1) << 16) | __bfloat16_as_ushort(h0);
    ph.y = ((uint32_t)__bfloat16_as_ushort(h3) << 16) | __bfloat16_as_ushort(h2);
    pl.x = ((uint32_t)__bfloat16_as_ushort(l1) << 16) | __bfloat16_as_ushort(l0);
    pl.y = ((uint32_t)__bfloat16_as_ushort(l3) << 16) | __bfloat16_as_ushort(l2);
    *(uint2*)(g_x_hi + i) = ph;
    *(uint2*)(g_x_lo + i) = pl;
}

// src [E][R][C] fp32 -> dst [E][C][R] split bf16 (which: 0=W1, 1=W2)
__global__ void transpose_split_kernel(const float* __restrict__ src, int R, int C, int which) {
    __shared__ float tile[32][33];
    const int e = blockIdx.z;
    const int c0 = blockIdx.x * 32, r0 = blockIdx.y * 32;
    const int tx = threadIdx.x, ty = threadIdx.y;
    const float* s = src + (size_t)e * R * C;
    #pragma unroll
    for (int i = 0; i < 32; i += 8)
        tile[ty + i][tx] = s[(size_t)(r0 + ty + i) * C + c0 + tx];
    __syncthreads();
    __nv_bfloat16* dh = (which ? g_w2_hi : g_w1_hi) + (size_t)e * R * C;
    __nv_bfloat16* dl = (which ? g_w2_lo : g_w1_lo) + (size_t)e * R * C;
    #pragma unroll
    for (int i = 0; i < 32; i += 8) {
        float v = tile[tx][ty + i];
        __nv_bfloat16 h, l;
        split2(v, h, l);
        dh[(size_t)(c0 + ty + i) * R + r0 + tx] = h;
        dl[(size_t)(c0 + ty + i) * R + r0 + tx] = l;
    }
}

// ---------------- router ----------------------------------------------------
__global__ void pool_part_kernel(const float* __restrict__ x) {
    const int b = blockIdx.x, ch = blockIdx.y;
    const float* xb = x + ((size_t)b * TT + ch * 32) * DD;
    for (int d = threadIdx.x; d < DD; d += 256) {
        float s = 0.f;
        #pragma unroll
        for (int t = 0; t < 32; t++) s += xb[(size_t)t * DD + d];
        g_pool_part[b][ch][d] = s;
    }
}

__global__ void router_kernel(const float* __restrict__ Wp, const float* __restrict__ bp,
                              float* __restrict__ out, int write_aux) {
    __shared__ float pooled[DD];
    __shared__ float logits[EE];
    const int b = blockIdx.x;
    for (int d = threadIdx.x; d < DD; d += 256) {
        float s = 0.f;
        #pragma unroll
        for (int ch = 0; ch < 16; ch++) s += g_pool_part[b][ch][d];
        pooled[d] = s * (1.0f / TT);
    }
    __syncthreads();
    const int warp = threadIdx.x >> 5, lane = threadIdx.x & 31;
    if (warp < EE) {
        float s = 0.f;
        for (int d = lane; d < DD; d += 32) s += pooled[d] * Wp[d * EE + warp];
        #pragma unroll
        for (int o = 16; o > 0; o >>= 1) s += __shfl_xor_sync(0xFFFFFFFFu, s, o);
        if (lane == 0) logits[warp] = s + bp[warp];
    }
    __syncthreads();
    if (threadIdx.x == 0) {
        float mx = logits[0]; int arg = 0;
        #pragma unroll
        for (int e = 1; e < EE; e++) if (logits[e] > mx) { mx = logits[e]; arg = e; }
        float ex[EE], den = 0.f;
        #pragma unroll
        for (int e = 0; e < EE; e++) { ex[e] = expf(logits[e] - mx); den += ex[e]; }
        if (write_aux) {
            const float inv = 1.0f / den;
            #pragma unroll
            for (int e = 0; e < EE; e++) out[FINAL_ELEMS + b * EE + e] = ex[e] * inv;
            out[FINAL_ELEMS + BB * EE + b] = (float)arg;
        }
        g_expert[b] = arg;
    }
}

// ---------------- HMMA GEMM (mma.sync, split-bf16 3-term) -------------------
// Block 128x128, KC=32 double-buffered cp.async stages, 8 warps (4Mx2N),
// warp tile 32x64 (2 m16 x 8 n8), XOR-swizzled smem for conflict-free ldmatrix.
#define KC 32
#define AHI_OFF 0
#define ALO_OFF 8192
#define BHI_OFF 16384
#define BLO_OFF 24576
#define STAGE_B 32768
#define SMEM_TOTAL (2 * STAGE_B)

// smem byte offset for (row r, 16B-chunk c) with swizzle
__device__ __forceinline__ uint32_t swoff(int r, int c) {
    return (uint32_t)(r * 64 + ((c ^ ((r >> 1) & 3)) << 4));
}

template<bool RELU, bool SPLIT_OUT>
__device__ __forceinline__ void gemm_hmma(
    const __nv_bfloat16* __restrict__ Ahi, const __nv_bfloat16* __restrict__ Alo,
    const __nv_bfloat16* __restrict__ Bhi, const __nv_bfloat16* __restrict__ Blo,
    const float* __restrict__ bias, int K,
    float* __restrict__ outF, __nv_bfloat16* __restrict__ outHi,
    __nv_bfloat16* __restrict__ outLo, int Nld) {

    extern __shared__ char smem[];
    const uint32_t sb = smem_u32(smem);
    const int tid = threadIdx.x;
    const int wid = tid >> 5, lane = tid & 31;
    const int wm = wid & 3, wn = wid >> 2;          // 4 x 2 warp grid
    const int row0 = blockIdx.y * 128;
    const int col0 = blockIdx.x * 128;

    float acc[2][8][4];
    #pragma unroll
    for (int i = 0; i < 2; i++)
        #pragma unroll
        for (int j = 0; j < 8; j++)
            #pragma unroll
            for (int k = 0; k < 4; k++) acc[i][j][k] = 0.f;

    const int nk = K / KC;
    const int sr = tid >> 2, sc = tid & 3;          // staging: 2 chunks per array

    // ---- stage helper (issued inline twice: prologue + loop) ----
    #define STAGE(IDX)                                                          \
    do {                                                                        \
        const int _i = (IDX);                                                   \
        const uint32_t _d = sb + (_i & 1) * STAGE_B;                            \
        const int _kb = _i * KC;                                                \
        _Pragma("unroll")                                                       \
        for (int it = 0; it < 2; it++) {                                        \
            const int r = sr + it * 64;                                         \
            const uint32_t so = swoff(r, sc);                                   \
            const size_t ga = (size_t)(row0 + r) * K + _kb + sc * 8;            \
            const size_t gb = (size_t)(col0 + r) * K + _kb + sc * 8;            \
            CP_ASYNC16(_d + AHI_OFF + so, Ahi + ga);                            \
            CP_ASYNC16(_d + ALO_OFF + so, Alo + ga);                            \
            CP_ASYNC16(_d + BHI_OFF + so, Bhi + gb);                            \
            CP_ASYNC16(_d + BLO_OFF + so, Blo + gb);                            \
        }                                                                       \
        CP_COMMIT();                                                            \
    } while (0)

    STAGE(0);

    // fragment address parameters (constant across loop)
    const int a_mrow = lane & 15, a_kh = lane >> 4;
    const int b_nr = lane & 7, b_kh = (lane >> 3) & 1, b_nt = lane >> 4;

    for (int i = 0; i < nk; i++) {
        if (i + 1 < nk) { STAGE(i + 1); CP_WAIT(1); }
        else            { CP_WAIT(0); }
        __syncthreads();

        const uint32_t st = sb + (i & 1) * STAGE_B;
        #pragma unroll
        for (int ks = 0; ks < 2; ks++) {
            uint32_t ah[2][4], al[2][4];
            #pragma unroll
            for (int mt = 0; mt < 2; mt++) {
                const int r = wm * 32 + mt * 16 + a_mrow;
                const uint32_t ad = st + swoff(r, ks * 2 + a_kh);
                ldsm4(ah[mt], ad + AHI_OFF);
                ldsm4(al[mt], ad + ALO_OFF);
            }
            uint32_t bh[8][2], bl[8][2];
            #pragma unroll
            for (int ng = 0; ng < 4; ng++) {
                const int r = wn * 64 + ng * 16 + b_nt * 8 + b_nr;
                const uint32_t bd = st + swoff(r, ks * 2 + b_kh);
                uint32_t t4[4];
                ldsm4(t4, bd + BHI_OFF);
                bh[ng * 2][0] = t4[0]; bh[ng * 2][1] = t4[1];
                bh[ng * 2 + 1][0] = t4[2]; bh[ng * 2 + 1][1] = t4[3];
                ldsm4(t4, bd + BLO_OFF);
                bl[ng * 2][0] = t4[0]; bl[ng * 2][1] = t4[1];
                bl[ng * 2 + 1][0] = t4[2]; bl[ng * 2 + 1][1] = t4[3];
            }
            #pragma unroll
            for (int mt = 0; mt < 2; mt++)
                #pragma unroll
                for (int nt = 0; nt < 8; nt++) {
                    mma16816(acc[mt][nt], ah[mt], bh[nt]);   // hi*hi
                    mma16816(acc[mt][nt], ah[mt], bl[nt]);   // hi*lo
                    mma16816(acc[mt][nt], al[mt], bh[nt]);   // lo*hi
                }
        }
        __syncthreads();
    }
    #undef STAGE

    // ---- epilogue: bias (+relu), direct stores ----
    const int erow = lane >> 2, ecol = (lane & 3) * 2;
    #pragma unroll
    for (int mt = 0; mt < 2; mt++) {
        #pragma unroll
        for (int nt = 0; nt < 8; nt++) {
            const int col = col0 + wn * 64 + nt * 8 + ecol;
            const float bx = __ldg(bias + col), by = __ldg(bias + col + 1);
            float v[4];
            v[0] = acc[mt][nt][0] + bx; v[1] = acc[mt][nt][1] + by;
            v[2] = acc[mt][nt][2] + bx; v[3] = acc[mt][nt][3] + by;
            if (RELU) {
                #pragma unroll
                for (int q = 0; q < 4; q++) v[q] = fmaxf(v[q], 0.f);
            }
            const size_t r0g = (size_t)(row0 + wm * 32 + mt * 16 + erow);
            #pragma unroll
            for (int half = 0; half < 2; half++) {
                const size_t row = r0g + half * 8;
                const float v0 = v[half * 2], v1 = v[half * 2 + 1];
                if (SPLIT_OUT) {
                    __nv_bfloat16 h0, l0, h1, l1;
                    split2(v0, h0, l0); split2(v1, h1, l1);
                    *(uint32_t*)(outHi + row * Nld + col) =
                        ((uint32_t)__bfloat16_as_ushort(h1) << 16) | __bfloat16_as_ushort(h0);
                    *(uint32_t*)(outLo + row * Nld + col) =
                        ((uint32_t)__bfloat16_as_ushort(l1) << 16) | __bfloat16_as_ushort(l0);
                } else {
                    float2 f2; f2.x = v0; f2.y = v1;
                    *(float2*)(outF + row * Nld + col) = f2;
                }
            }
        }
    }
}

// GEMM1: h = relu(x @ W1[e] + b1[e])   M=512, N=2048, K=512
__global__ void __launch_bounds__(256, 1)
gemm1_mm(const float* __restrict__ b1) {
    const int b = blockIdx.z;
    const int e = g_expert[b];
    gemm_hmma<true, true>(g_x_hi + (size_t)b * TT * DD, g_x_lo + (size_t)b * TT * DD,
                          g_w1_hi + (size_t)e * HH * DD, g_w1_lo + (size_t)e * HH * DD,
                          b1 + e * HH, DD,
                          nullptr, g_h_hi + (size_t)b * TT * HH, g_h_lo + (size_t)b * TT * HH, HH);
}

// GEMM2: out = h @ W2[e] + b2[e]       M=512, N=512, K=2048
__global__ void __launch_bounds__(256, 1)
gemm2_mm(const float* __restrict__ b2, float* __restrict__ out) {
    const int b = blockIdx.z;
    const int e = g_expert[b];
    gemm_hmma<false, false>(g_h_hi + (size_t)b * TT * HH, g_h_lo + (size_t)b * TT * HH,
                            g_w2_hi + (size_t)e * DD * HH, g_w2_lo + (size_t)e * DD * HH,
                            b2 + e * DD, HH,
                            out + (size_t)b * TT * DD, nullptr, nullptr, DD);
}

// ---------------- launch ----------------------------------------------------
extern "C" void kernel_launch(void* const* d_in, const int* in_sizes, int n_in,
                              void* d_out, int out_size) {
    const float* x  = (const float*)d_in[0];
    const float* Wp = (const float*)d_in[1];
    const float* bp = (const float*)d_in[2];
    const float* W1 = (const float*)d_in[3];
    const float* b1 = (const float*)d_in[4];
    const float* W2 = (const float*)d_in[5];
    const float* b2 = (const float*)d_in[6];
    float* out = (float*)d_out;

    const int write_aux = (out_size >= FINAL_ELEMS + BB * EE + BB) ? 1 : 0;

    cudaFuncSetAttribute(gemm1_mm, cudaFuncAttributeMaxDynamicSharedMemorySize, SMEM_TOTAL);
    cudaFuncSetAttribute(gemm2_mm, cudaFuncAttributeMaxDynamicSharedMemorySize, SMEM_TOTAL);

    split_x_kernel<<<(BB * TT * DD) / 4 / 256, 256>>>(x);
    transpose_split_kernel<<<dim3(HH / 32, DD / 32, EE), dim3(32, 8)>>>(W1, DD, HH, 0);
    transpose_split_kernel<<<dim3(DD / 32, HH / 32, EE), dim3(32, 8)>>>(W2, HH, DD, 1);
    pool_part_kernel<<<dim3(BB, 16), 256>>>(x);
    router_kernel<<<BB, 256>>>(Wp, bp, out, write_aux);
    gemm1_mm<<<dim3(HH / 128, TT / 128, BB), 256, SMEM_TOTAL>>>(b1);
    gemm2_mm<<<dim3(DD / 128, TT / 128, BB), 256, SMEM_TOTAL>>>(b2, out);
}